// round 2
// baseline (speedup 1.0000x reference)
#include <cuda_runtime.h>
#include <cuda_bf16.h>

// Batched per-sample MLP: B=32, 1024 -> 2048 (relu) -> 2048 (relu) -> 1024 (linear)
// Each sample b has its own flattened params[b, P].
// Pure HBM-bound GEMV chain; threads map to output neurons (coalesced W reads),
// input activation staged in shared memory.

#define BATCH 32
#define L0 1024
#define L1 2048
#define L2 2048
#define L3 1024

// Per-sample param layout offsets (fp32 elements)
#define W1_OFF 0LL
#define B1_OFF (W1_OFF + (long long)L0 * L1)          // 2097152
#define W2_OFF (B1_OFF + L1)                          // 2099200
#define B2_OFF (W2_OFF + (long long)L1 * L2)          // 6293504
#define W3_OFF (B2_OFF + L2)                          // 6295552
#define B3_OFF (W3_OFF + (long long)L2 * L3)          // 8392704
#define P_LEN  (B3_OFF + L3)                          // 8393728

// Intermediate activations (device globals — no allocations allowed)
__device__ float g_act1[BATCH * L1];
__device__ float g_act2[BATCH * L2];

template <int IN, int OUT, int BLOCK, bool RELU>
__global__ void __launch_bounds__(BLOCK)
mlp_layer_kernel(const float* __restrict__ params,
                 long long w_off, long long b_off,
                 const float* __restrict__ x_in,
                 float* __restrict__ x_out)
{
    __shared__ float sx[IN];

    const int b = blockIdx.y;
    const int o = blockIdx.x * BLOCK + threadIdx.x;

    // Stage this sample's input vector into shared memory (vectorized).
    const float4* xv = reinterpret_cast<const float4*>(x_in + (long long)b * IN);
    #pragma unroll
    for (int i = threadIdx.x; i < IN / 4; i += BLOCK) {
        float4 v = xv[i];
        sx[4 * i + 0] = v.x;
        sx[4 * i + 1] = v.y;
        sx[4 * i + 2] = v.z;
        sx[4 * i + 3] = v.w;
    }
    __syncthreads();

    const float* __restrict__ W = params + (long long)b * P_LEN + w_off;
    const float* __restrict__ Bv = params + (long long)b * P_LEN + b_off;

    float acc = 0.0f;
    // W[i*OUT + o]: consecutive threads read consecutive addresses -> full
    // 128B cacheline per warp per iteration. Unroll to batch LDGs (MLP).
    #pragma unroll 16
    for (int i = 0; i < IN; ++i) {
        acc = fmaf(sx[i], __ldg(&W[(long long)i * OUT + o]), acc);
    }

    acc += __ldg(&Bv[o]);
    if (RELU) acc = fmaxf(acc, 0.0f);
    x_out[(long long)b * OUT + o] = acc;
}

extern "C" void kernel_launch(void* const* d_in, const int* in_sizes, int n_in,
                              void* d_out, int out_size)
{
    const float* params = (const float*)d_in[0];  // (B, P) fp32
    const float* x      = (const float*)d_in[1];  // (B, 1024) fp32
    float* out          = (float*)d_out;          // (B, 1024) fp32

    float* act1;
    float* act2;
    cudaGetSymbolAddress((void**)&act1, g_act1);
    cudaGetSymbolAddress((void**)&act2, g_act2);

    // Layer 1: 1024 -> 2048, relu.  grid = (2048/256, 32) = 256 CTAs
    {
        dim3 grid(L1 / 256, BATCH);
        mlp_layer_kernel<L0, L1, 256, true><<<grid, 256>>>(params, W1_OFF, B1_OFF, x, act1);
    }
    // Layer 2: 2048 -> 2048, relu.  grid = 256 CTAs
    {
        dim3 grid(L2 / 256, BATCH);
        mlp_layer_kernel<L1, L2, 256, true><<<grid, 256>>>(params, W2_OFF, B2_OFF, act1, act2);
    }
    // Layer 3: 2048 -> 1024, linear. 128-thread blocks -> (1024/128)*32 = 256 CTAs
    {
        dim3 grid(L3 / 128, BATCH);
        mlp_layer_kernel<L2, L3, 128, false><<<grid, 128>>>(params, W3_OFF, B3_OFF, act2, out);
    }
}

// round 3
// speedup vs baseline: 1.0010x; 1.0010x over previous
#include <cuda_runtime.h>
#include <cuda_bf16.h>

// Batched per-sample MLP: B=32, 1024 -> 2048 (relu) -> 2048 (relu) -> 1024 (linear)
// Each sample b has its own flattened params[b, P].
// Pure HBM-bound GEMV chain; threads map to output neurons (coalesced W reads),
// input activation staged in shared memory.

#define BATCH 32
#define L0 1024
#define L1 2048
#define L2 2048
#define L3 1024

// Per-sample param layout offsets (fp32 elements)
#define W1_OFF 0LL
#define B1_OFF (W1_OFF + (long long)L0 * L1)          // 2097152
#define W2_OFF (B1_OFF + L1)                          // 2099200
#define B2_OFF (W2_OFF + (long long)L1 * L2)          // 6293504
#define W3_OFF (B2_OFF + L2)                          // 6295552
#define B3_OFF (W3_OFF + (long long)L2 * L3)          // 8392704
#define P_LEN  (B3_OFF + L3)                          // 8393728

// Intermediate activations (device globals — no allocations allowed)
__device__ float g_act1[BATCH * L1];
__device__ float g_act2[BATCH * L2];

template <int IN, int OUT, int BLOCK, bool RELU>
__global__ void __launch_bounds__(BLOCK)
mlp_layer_kernel(const float* __restrict__ params,
                 long long w_off, long long b_off,
                 const float* __restrict__ x_in,
                 float* __restrict__ x_out)
{
    __shared__ float sx[IN];

    const int b = blockIdx.y;
    const int o = blockIdx.x * BLOCK + threadIdx.x;

    // Stage this sample's input vector into shared memory (vectorized).
    const float4* xv = reinterpret_cast<const float4*>(x_in + (long long)b * IN);
    #pragma unroll
    for (int i = threadIdx.x; i < IN / 4; i += BLOCK) {
        float4 v = xv[i];
        sx[4 * i + 0] = v.x;
        sx[4 * i + 1] = v.y;
        sx[4 * i + 2] = v.z;
        sx[4 * i + 3] = v.w;
    }
    __syncthreads();

    const float* __restrict__ W = params + (long long)b * P_LEN + w_off;
    const float* __restrict__ Bv = params + (long long)b * P_LEN + b_off;

    float acc = 0.0f;
    // W[i*OUT + o]: consecutive threads read consecutive addresses -> full
    // 128B cacheline per warp per iteration. Unroll to batch LDGs (MLP).
    #pragma unroll 16
    for (int i = 0; i < IN; ++i) {
        acc = fmaf(sx[i], __ldg(&W[(long long)i * OUT + o]), acc);
    }

    acc += __ldg(&Bv[o]);
    if (RELU) acc = fmaxf(acc, 0.0f);
    x_out[(long long)b * OUT + o] = acc;
}

extern "C" void kernel_launch(void* const* d_in, const int* in_sizes, int n_in,
                              void* d_out, int out_size)
{
    const float* params = (const float*)d_in[0];  // (B, P) fp32
    const float* x      = (const float*)d_in[1];  // (B, 1024) fp32
    float* out          = (float*)d_out;          // (B, 1024) fp32

    float* act1;
    float* act2;
    cudaGetSymbolAddress((void**)&act1, g_act1);
    cudaGetSymbolAddress((void**)&act2, g_act2);

    // Layer 1: 1024 -> 2048, relu.  grid = (2048/256, 32) = 256 CTAs
    {
        dim3 grid(L1 / 256, BATCH);
        mlp_layer_kernel<L0, L1, 256, true><<<grid, 256>>>(params, W1_OFF, B1_OFF, x, act1);
    }
    // Layer 2: 2048 -> 2048, relu.  grid = 256 CTAs
    {
        dim3 grid(L2 / 256, BATCH);
        mlp_layer_kernel<L1, L2, 256, true><<<grid, 256>>>(params, W2_OFF, B2_OFF, act1, act2);
    }
    // Layer 3: 2048 -> 1024, linear. 128-thread blocks -> (1024/128)*32 = 256 CTAs
    {
        dim3 grid(L3 / 128, BATCH);
        mlp_layer_kernel<L2, L3, 128, false><<<grid, 128>>>(params, W3_OFF, B3_OFF, act2, out);
    }
}

// round 4
// speedup vs baseline: 1.8609x; 1.8590x over previous
#include <cuda_runtime.h>
#include <cuda_bf16.h>

// Batched per-sample MLP: B=32, 1024 -> 2048 (relu) -> 2048 (relu) -> 1024 (linear)
// HBM-bound GEMV chain. Round 3: float4 weight loads (4 outputs/thread, 512B/warp
// per LDG) + split-K via atomicAdd for CTA supply / occupancy. ReLU folded into
// the consumer's smem staging so accumulation stays linear.

#define BATCH 32
#define L0 1024
#define L1 2048
#define L2 2048
#define L3 1024

// Per-sample param layout offsets (fp32 elements)
#define W1_OFF 0LL
#define B1_OFF (W1_OFF + (long long)L0 * L1)          // 2097152
#define W2_OFF (B1_OFF + L1)                          // 2099200
#define B2_OFF (W2_OFF + (long long)L1 * L2)          // 6293504
#define B3W_OFF (B2_OFF + L2)                         // W3 at 6295552
#define W3_OFF (B2_OFF + L2)
#define B3_OFF (W3_OFF + (long long)L2 * L3)          // 8392704
#define P_LEN  (B3_OFF + L3)                          // 8393728

// Intermediate activations (device globals — no allocations allowed)
__device__ float g_act1[BATCH * L1];
__device__ float g_act2[BATCH * L2];

// One CTA: BLOCK threads, each computing 4 consecutive outputs over a CHUNK of
// the input dimension; partial sums accumulated into y via atomicAdd.
// RELU_IN: apply relu to x_in while staging (x_in holds pre-activation sums).
template <int IN, int OUT, int CHUNK, int BLOCK, bool RELU_IN>
__global__ void __launch_bounds__(BLOCK)
mlp_layer_splitk(const float* __restrict__ params,
                 long long w_off, long long b_off,
                 const float* __restrict__ x_in,
                 float* __restrict__ y_out)
{
    __shared__ float sx[CHUNK];

    const int b   = blockIdx.y;
    const int ks  = blockIdx.z;
    const int i0  = ks * CHUNK;
    const int o4  = (blockIdx.x * BLOCK + threadIdx.x) * 4;

    // Stage this CTA's input chunk, applying relu if needed.
    const float* __restrict__ xb = x_in + (long long)b * IN + i0;
    for (int i = threadIdx.x; i < CHUNK; i += BLOCK) {
        float v = __ldg(&xb[i]);
        if (RELU_IN) v = fmaxf(v, 0.0f);
        sx[i] = v;
    }
    __syncthreads();

    const float* __restrict__ Wb =
        params + (long long)b * P_LEN + w_off + (long long)i0 * OUT + o4;

    float ax = 0.f, ay = 0.f, az = 0.f, aw = 0.f;
    // First split adds the bias (exactly once per output).
    if (ks == 0) {
        const float* __restrict__ Bv = params + (long long)b * P_LEN + b_off + o4;
        float4 bv = __ldg(reinterpret_cast<const float4*>(Bv));
        ax = bv.x; ay = bv.y; az = bv.z; aw = bv.w;
    }

    // Inner loop: one LDG.128 per thread per i (512B/warp), 8-deep unroll for MLP.
    #pragma unroll 8
    for (int i = 0; i < CHUNK; ++i) {
        float4 w = __ldg(reinterpret_cast<const float4*>(Wb + (long long)i * OUT));
        float s = sx[i];
        ax = fmaf(s, w.x, ax);
        ay = fmaf(s, w.y, ay);
        az = fmaf(s, w.z, az);
        aw = fmaf(s, w.w, aw);
    }

    float* y = y_out + (long long)b * OUT + o4;
    atomicAdd(y + 0, ax);
    atomicAdd(y + 1, ay);
    atomicAdd(y + 2, az);
    atomicAdd(y + 3, aw);
}

extern "C" void kernel_launch(void* const* d_in, const int* in_sizes, int n_in,
                              void* d_out, int out_size)
{
    const float* params = (const float*)d_in[0];  // (B, P) fp32
    const float* x      = (const float*)d_in[1];  // (B, 1024) fp32
    float* out          = (float*)d_out;          // (B, 1024) fp32

    float* act1;
    float* act2;
    cudaGetSymbolAddress((void**)&act1, g_act1);
    cudaGetSymbolAddress((void**)&act2, g_act2);

    // Zero accumulation targets (graph-capturable memset nodes).
    cudaMemsetAsync(act1, 0, sizeof(float) * BATCH * L1);
    cudaMemsetAsync(act2, 0, sizeof(float) * BATCH * L2);
    cudaMemsetAsync(out,  0, sizeof(float) * BATCH * L3);

    // Layer 1: 1024 -> 2048. tiles = 2048/(256*4) = 2, KS = 8 (chunk 128) -> 512 CTAs.
    {
        dim3 grid(L1 / (256 * 4), BATCH, L0 / 128);
        mlp_layer_splitk<L0, L1, 128, 256, false><<<grid, 256>>>(
            params, W1_OFF, B1_OFF, x, act1);
    }
    // Layer 2: 2048 -> 2048. tiles = 2, KS = 8 (chunk 256) -> 512 CTAs. relu on read.
    {
        dim3 grid(L2 / (256 * 4), BATCH, L1 / 256);
        mlp_layer_splitk<L1, L2, 256, 256, true><<<grid, 256>>>(
            params, W2_OFF, B2_OFF, act1, act2);
    }
    // Layer 3: 2048 -> 1024. tiles = 1, KS = 16 (chunk 128) -> 512 CTAs. relu on read.
    {
        dim3 grid(L3 / (256 * 4), BATCH, L2 / 128);
        mlp_layer_splitk<L2, L3, 128, 256, true><<<grid, 256>>>(
            params, W3_OFF, B3_OFF, act2, out);
    }
}